// round 14
// baseline (speedup 1.0000x reference)
#include <cuda_runtime.h>
#include <cuda_fp16.h>
#include <cstdint>

#define B_SZ 2
#define N_SZ 2048
#define D_SZ 2048
#define H_SZ 16
#define HD_SZ 128
#define M_SZ (B_SZ * N_SZ)   // 4096

// Tiled operand layout: 16KB blocks [128 rows x 64 cols f16], row stride
// 128 B, 16B-group swizzle c8 ^= (r & 7). Block id = panel*32 + kchunk.
#define TB 16384

// Scratch (static device arrays; no allocation allowed)
__device__ float g_q[M_SZ * D_SZ];
__device__ float g_k[M_SZ * D_SZ];
__device__ float g_v[M_SZ * D_SZ];
__device__ __align__(128) __half g_xh[M_SZ * D_SZ];
__device__ __align__(128) __half g_xl[M_SZ * D_SZ];
__device__ __align__(128) __half g_wh[4 * D_SZ * D_SZ];
__device__ __align__(128) __half g_oh[M_SZ * D_SZ];
__device__ __align__(128) __half g_qh[M_SZ * D_SZ];
__device__ __align__(128) __half g_kh[M_SZ * D_SZ];
__device__ __align__(128) __half g_vh[M_SZ * D_SZ];

// ===========================================================================
// PTX helpers (sm_80/sm_90 base-arch: legal at compute_103)
// ===========================================================================
__device__ __forceinline__ uint32_t smem_u32(const void* p) {
    uint32_t a;
    asm("{ .reg .u64 t; cvta.to.shared.u64 t, %1; cvt.u32.u64 %0, t; }"
        : "=r"(a) : "l"(p));
    return a;
}

__device__ __forceinline__ void ldsm_x4(uint32_t& r0, uint32_t& r1,
                                        uint32_t& r2, uint32_t& r3,
                                        uint32_t addr) {
    asm volatile("ldmatrix.sync.aligned.m8n8.x4.shared.b16 {%0,%1,%2,%3}, [%4];"
                 : "=r"(r0), "=r"(r1), "=r"(r2), "=r"(r3) : "r"(addr));
}

__device__ __forceinline__ void ldsm_x4_t(uint32_t& r0, uint32_t& r1,
                                          uint32_t& r2, uint32_t& r3,
                                          uint32_t addr) {
    asm volatile("ldmatrix.sync.aligned.m8n8.x4.trans.shared.b16 {%0,%1,%2,%3}, [%4];"
                 : "=r"(r0), "=r"(r1), "=r"(r2), "=r"(r3) : "r"(addr));
}

__device__ __forceinline__ void mma_f16(float* d, const uint32_t* a,
                                        uint32_t b0, uint32_t b1) {
    asm volatile(
        "mma.sync.aligned.m16n8k16.row.col.f32.f16.f16.f32 "
        "{%0,%1,%2,%3}, {%4,%5,%6,%7}, {%8,%9}, {%0,%1,%2,%3};"
        : "+f"(d[0]), "+f"(d[1]), "+f"(d[2]), "+f"(d[3])
        : "r"(a[0]), "r"(a[1]), "r"(a[2]), "r"(a[3]), "r"(b0), "r"(b1));
}

// Non-tensor bulk TMA: contiguous global -> contiguous shared
#define CP_BULK(saddr, gptr, bytes, mbar) \
    asm volatile( \
        "cp.async.bulk.shared::cta.global.mbarrier::complete_tx::bytes " \
        "[%0], [%1], %2, [%3];" \
        :: "r"(saddr), "l"(gptr), "r"(bytes), "r"(mbar) : "memory")

#define MBARRIER_INIT(mbar, count) \
    asm volatile("mbarrier.init.shared.b64 [%0], %1;" \
                 :: "r"(mbar), "r"((uint32_t)(count)) : "memory")

#define MBARRIER_EXPECT_TX(mbar, bytes) \
    asm volatile("mbarrier.arrive.expect_tx.shared.b64 _, [%0], %1;" \
                 :: "r"(mbar), "r"((uint32_t)(bytes)) : "memory")

#define MBARRIER_WAIT_PARITY(mbar, parity) do { \
    uint32_t _mb = (mbar); \
    uint32_t _ph = (parity); \
    asm volatile( \
        "{\n\t" \
        ".reg .pred P1;\n\t" \
        "WAIT_LOOP_%=:\n\t" \
        "mbarrier.try_wait.parity.acquire.cta.shared::cta.b64 P1, [%0], %1, 0x989680;\n\t" \
        "@P1 bra.uni WAIT_DONE_%=;\n\t" \
        "bra.uni WAIT_LOOP_%=;\n\t" \
        "WAIT_DONE_%=:\n\t" \
        "}" \
        :: "r"(_mb), "r"(_ph) : "memory"); \
} while (0)

#define FENCE_PROXY_ASYNC() \
    asm volatile("fence.proxy.async.shared::cta;" ::: "memory")

// pack two fp32 -> f16x2 (e0 low, e1 high)
__device__ __forceinline__ uint32_t pack2h(float e0, float e1) {
    __half2 h = __floats2half2_rn(e0, e1);
    return *(uint32_t*)&h;
}

__device__ __forceinline__ void split2h(float e0, float e1,
                                        uint32_t& h, uint32_t& l) {
    h = pack2h(e0, e1);
    __half2 hh = *(__half2*)&h;
    l = pack2h(e0 - __low2float(hh), e1 - __high2float(hh));
}

__device__ __forceinline__ void split4h(float4 f, uint2& hi, uint2& lo) {
    split2h(f.x, f.y, hi.x, lo.x);
    split2h(f.z, f.w, hi.y, lo.y);
}

// Fast exp2 on the FMA pipe
__device__ __forceinline__ float exp2p(float y) {
    y = fmaxf(y, -126.0f);
    int n = __float2int_rd(y);
    float f = y - (float)n;
    float r = 1.8775767e-3f;
    r = fmaf(r, f, 8.9893397e-3f);
    r = fmaf(r, f, 5.5826318e-2f);
    r = fmaf(r, f, 2.4015361e-1f);
    r = fmaf(r, f, 6.9315308e-1f);
    r = fmaf(r, f, 1.0f);
    return r * __int_as_float((n + 127) << 23);
}

#define LOG2E 1.4426950408889634f

// ===========================================================================
// Split kernels: fp32 [nrows x 2048] -> tiled/swizzled fp16
// ===========================================================================
__global__ __launch_bounds__(256) void split_tiled(
    const float* __restrict__ src, __half* __restrict__ hi,
    __half* __restrict__ lo, int nrows) {
    int idx = blockIdx.x * 256 + threadIdx.x;
    if (idx >= nrows * 256) return;
    int rg = idx >> 8;
    int g = idx & 255;
    int kc = g >> 3, c8 = g & 7;
    int panel = rg >> 7, r = rg & 127;

    const float4* s = (const float4*)(src + (size_t)rg * 2048 + kc * 64 + c8 * 8);
    float4 f0 = s[0], f1 = s[1];
    uint2 h0, l0, h1, l1;
    split4h(f0, h0, l0);
    split4h(f1, h1, l1);

    size_t off = (size_t)(panel * 32 + kc) * TB
               + (uint32_t)(r * 128 + ((c8 ^ (r & 7)) << 4));
    *(uint4*)((char*)hi + off) = make_uint4(h0.x, h0.y, h1.x, h1.y);
    *(uint4*)((char*)lo + off) = make_uint4(l0.x, l0.y, l1.x, l1.y);
}

// All four weights in one launch: blockIdx.y selects src / dst slice.
__global__ __launch_bounds__(256) void split_tiled_w(
    const float* __restrict__ w0, const float* __restrict__ w1,
    const float* __restrict__ w2, const float* __restrict__ w3,
    __half* __restrict__ hi) {
    int idx = blockIdx.x * 256 + threadIdx.x;
    int wz = blockIdx.y;
    const float* src = (wz == 0) ? w0 : (wz == 1) ? w1 : (wz == 2) ? w2 : w3;
    int rg = idx >> 8;
    int g = idx & 255;
    int kc = g >> 3, c8 = g & 7;
    int panel = rg >> 7, r = rg & 127;

    const float4* s = (const float4*)(src + (size_t)rg * 2048 + kc * 64 + c8 * 8);
    float4 f0 = s[0], f1 = s[1];

    size_t off = (size_t)wz * (D_SZ * D_SZ) * 2
               + (size_t)(panel * 32 + kc) * TB
               + (uint32_t)(r * 128 + ((c8 ^ (r & 7)) << 4));
    *(uint4*)((char*)hi + off) = make_uint4(pack2h(f0.x, f0.y), pack2h(f0.z, f0.w),
                                            pack2h(f1.x, f1.y), pack2h(f1.z, f1.w));
}

// ===========================================================================
// rope_convert: read fp32 q/k/v, apply RoPE to q/k (+1/sqrt(d) scale on q),
// write tiled/swizzled fp16: Q hi, K hi, V hi.
// ===========================================================================
__global__ __launch_bounds__(256) void rope_convert(
    const float* __restrict__ q, const float* __restrict__ k,
    const float* __restrict__ v,
    __half* __restrict__ qh, __half* __restrict__ kh, __half* __restrict__ vh) {
    int idx = blockIdx.x * 256 + threadIdx.x;     // M*16*8 = 524288
    int rg = idx >> 7;
    int rem = idx & 127;
    int h = rem >> 3, c8 = rem & 7;
    int pos = rg & (N_SZ - 1);
    int panel = rg >> 7, r = rg & 127;
    const float sc = 0.08838834764831845f;

    float cc[8], ss[8];
#pragma unroll
    for (int e = 0; e < 8; e++) {
        int i = c8 * 8 + e;
        float inv_freq = powf(10000.0f, -(float)i * (1.0f / 64.0f));
        sincosf((float)pos * inv_freq, &ss[e], &cc[e]);
    }

    size_t base = (size_t)rg * D_SZ + h * HD_SZ + c8 * 8;
    float q1[8], q2[8], k1[8], k2[8], v1[8], v2[8];
    *(float4*)&q1[0] = *(const float4*)(q + base);
    *(float4*)&q1[4] = *(const float4*)(q + base + 4);
    *(float4*)&q2[0] = *(const float4*)(q + base + 64);
    *(float4*)&q2[4] = *(const float4*)(q + base + 68);
    *(float4*)&k1[0] = *(const float4*)(k + base);
    *(float4*)&k1[4] = *(const float4*)(k + base + 4);
    *(float4*)&k2[0] = *(const float4*)(k + base + 64);
    *(float4*)&k2[4] = *(const float4*)(k + base + 68);
    *(float4*)&v1[0] = *(const float4*)(v + base);
    *(float4*)&v1[4] = *(const float4*)(v + base + 4);
    *(float4*)&v2[0] = *(const float4*)(v + base + 64);
    *(float4*)&v2[4] = *(const float4*)(v + base + 68);

    float qo1[8], qo2[8], ko1[8], ko2[8];
#pragma unroll
    for (int e = 0; e < 8; e++) {
        qo1[e] = (q1[e] * cc[e] - q2[e] * ss[e]) * sc;
        qo2[e] = (q2[e] * cc[e] + q1[e] * ss[e]) * sc;
        ko1[e] = k1[e] * cc[e] - k2[e] * ss[e];
        ko2[e] = k2[e] * cc[e] + k1[e] * ss[e];
    }

    uint32_t inoff = (uint32_t)(r * 128 + ((c8 ^ (r & 7)) << 4));
    size_t b0 = (size_t)(panel * 32 + 2 * h) * TB + inoff;
    size_t b1 = b0 + TB;

    *(uint4*)((char*)qh + b0) = make_uint4(pack2h(qo1[0], qo1[1]), pack2h(qo1[2], qo1[3]),
                                           pack2h(qo1[4], qo1[5]), pack2h(qo1[6], qo1[7]));
    *(uint4*)((char*)qh + b1) = make_uint4(pack2h(qo2[0], qo2[1]), pack2h(qo2[2], qo2[3]),
                                           pack2h(qo2[4], qo2[5]), pack2h(qo2[6], qo2[7]));
    *(uint4*)((char*)kh + b0) = make_uint4(pack2h(ko1[0], ko1[1]), pack2h(ko1[2], ko1[3]),
                                           pack2h(ko1[4], ko1[5]), pack2h(ko1[6], ko1[7]));
    *(uint4*)((char*)kh + b1) = make_uint4(pack2h(ko2[0], ko2[1]), pack2h(ko2[2], ko2[3]),
                                           pack2h(ko2[4], ko2[5]), pack2h(ko2[6], ko2[7]));
    *(uint4*)((char*)vh + b0) = make_uint4(pack2h(v1[0], v1[1]), pack2h(v1[2], v1[3]),
                                           pack2h(v1[4], v1[5]), pack2h(v1[6], v1[7]));
    *(uint4*)((char*)vh + b1) = make_uint4(pack2h(v2[0], v2[1]), pack2h(v2[2], v2[3]),
                                           pack2h(v2[4], v2[5]), pack2h(v2[6], v2[7]));
}

// ===========================================================================
// gemm7: C[M,Nn] = A @ W^T, fp16 2-MMA (A = hi+lo, W = hi). cp.async.bulk,
// 2-stage (96KB smem) -> 2 CTAs/SM. Used for Q/K/V projections.
// ===========================================================================
#define STB7   (3 * TB)
#define G7_MBAR (2 * STB7)
#define G7_SMEM (2 * STB7 + 32)    // 98336

__global__ __launch_bounds__(256, 2) void gemm7(
    const __half* __restrict__ Ah, const __half* __restrict__ Al,
    const __half* __restrict__ Wh,
    float* __restrict__ C0, float* __restrict__ C1, float* __restrict__ C2,
    int Nn) {
    extern __shared__ char dsm[];
    const uint32_t sb = smem_u32(dsm);

    const int tid = threadIdx.x;
    const int warp = tid >> 5;
    const int lane = tid & 31;
    const int mbase = (warp >> 2) * 64;
    const int nbase = (warp & 3) * 32;

    const int z = blockIdx.z;
    float* C = (z == 0) ? C0 : (z == 1) ? C1 : C2;
    const char* pAh = (const char*)Ah;
    const char* pAl = (const char*)Al;
    const char* pBh = (const char*)(Wh + (size_t)z * D_SZ * D_SZ);

    float acc[4][4][4];
#pragma unroll
    for (int i = 0; i < 4; i++)
#pragma unroll
        for (int j = 0; j < 4; j++)
#pragma unroll
            for (int e = 0; e < 4; e++) acc[i][j][e] = 0.0f;

    const uint32_t mb0 = sb + G7_MBAR;

    if (tid == 0) {
        MBARRIER_INIT(mb0, 1);
        MBARRIER_INIT(mb0 + 8, 1);
    }
    __syncthreads();

    auto issue = [&](int st, int kc) {
        uint32_t s0 = sb + st * STB7;
        uint32_t mb = mb0 + st * 8;
        size_t offA = (size_t)(blockIdx.y * 32 + kc) * TB;
        size_t offB = (size_t)(blockIdx.x * 32 + kc) * TB;
        MBARRIER_EXPECT_TX(mb, 3 * TB);
        CP_BULK(s0,          pAh + offA, TB, mb);
        CP_BULK(s0 + TB,     pAl + offA, TB, mb);
        CP_BULK(s0 + 2 * TB, pBh + offB, TB, mb);
    };

    if (tid == 0) {
        issue(0, 0);
        issue(1, 1);
    }

    const int g = lane >> 3, lr = lane & 7;
    const uint32_t arow = (uint32_t)(mbase + lr + ((g & 1) << 3));
    const uint32_t brow = (uint32_t)(nbase + lr + ((g >> 1) << 3));
    const uint32_t aswz = arow & 7, bswz = brow & 7;

    for (int kc = 0; kc < 32; kc++) {
        const int st = kc & 1;
        MBARRIER_WAIT_PARITY(mb0 + st * 8, (kc >> 1) & 1);

        const uint32_t uAh = sb + st * STB7;
        const uint32_t uAl = uAh + TB;
        const uint32_t uBh = uAh + 2 * TB;

#pragma unroll
        for (int s = 0; s < 4; s++) {
            uint32_t c8a = (uint32_t)(s * 2 + (g >> 1));
            uint32_t c8b = (uint32_t)(s * 2 + (g & 1));
            uint32_t aoff = arow * 128 + ((c8a ^ aswz) << 4);
            uint32_t boff = brow * 128 + ((c8b ^ bswz) << 4);

            uint32_t ah[4][4], al[4][4];
#pragma unroll
            for (int mi = 0; mi < 4; mi++) {
                ldsm_x4(ah[mi][0], ah[mi][1], ah[mi][2], ah[mi][3],
                        uAh + aoff + mi * 2048);
                ldsm_x4(al[mi][0], al[mi][1], al[mi][2], al[mi][3],
                        uAl + aoff + mi * 2048);
            }
            uint32_t bh[8];
            ldsm_x4(bh[0], bh[1], bh[2], bh[3], uBh + boff);
            ldsm_x4(bh[4], bh[5], bh[6], bh[7], uBh + boff + 2048);

#pragma unroll
            for (int mi = 0; mi < 4; mi++) {
#pragma unroll
                for (int ni = 0; ni < 4; ni++) {
                    mma_f16(acc[mi][ni], ah[mi], bh[ni * 2], bh[ni * 2 + 1]);
                    mma_f16(acc[mi][ni], al[mi], bh[ni * 2], bh[ni * 2 + 1]);
                }
            }
        }
        __syncthreads();
        if (kc + 2 < 32 && tid == 0) {
            FENCE_PROXY_ASYNC();
            issue(st, kc + 2);
        }
    }

    const int gid = lane >> 2, tig = lane & 3;
    const int rowA = blockIdx.y * 128 + mbase + gid;
    const int colA = blockIdx.x * 128 + nbase + tig * 2;
#pragma unroll
    for (int mi = 0; mi < 4; mi++) {
#pragma unroll
        for (int ni = 0; ni < 4; ni++) {
            float* c0 = C + (size_t)(rowA + mi * 16) * Nn + colA + ni * 8;
            float* c1 = C + (size_t)(rowA + mi * 16 + 8) * Nn + colA + ni * 8;
            c0[0] = acc[mi][ni][0];
            c0[1] = acc[mi][ni][1];
            c1[0] = acc[mi][ni][2];
            c1[1] = acc[mi][ni][3];
        }
    }
}

// ===========================================================================
// gemm8: single-MMA GEMM (A = hi only, W = hi). 2-stage 64KB -> 3 CTAs/SM.
// Used for the O projection.
// ===========================================================================
#define STB8   (2 * TB)
#define G8_MBAR (2 * STB8)
#define G8_SMEM (2 * STB8 + 32)    // 65568

__global__ __launch_bounds__(256, 3) void gemm8(
    const __half* __restrict__ Ah, const __half* __restrict__ Wh,
    float* __restrict__ C, int Nn) {
    extern __shared__ char dsm[];
    const uint32_t sb = smem_u32(dsm);

    const int tid = threadIdx.x;
    const int warp = tid >> 5;
    const int lane = tid & 31;
    const int mbase = (warp >> 2) * 64;
    const int nbase = (warp & 3) * 32;

    const char* pAh = (const char*)Ah;
    const char* pBh = (const char*)Wh;

    float acc[4][4][4];
#pragma unroll
    for (int i = 0; i < 4; i++)
#pragma unroll
        for (int j = 0; j < 4; j++)
#pragma unroll
            for (int e = 0; e < 4; e++) acc[i][j][e] = 0.0f;

    const uint32_t mb0 = sb + G8_MBAR;

    if (tid == 0) {
        MBARRIER_INIT(mb0, 1);
        MBARRIER_INIT(mb0 + 8, 1);
    }
    __syncthreads();

    auto issue = [&](int st, int kc) {
        uint32_t s0 = sb + st * STB8;
        uint32_t mb = mb0 + st * 8;
        size_t offA = (size_t)(blockIdx.y * 32 + kc) * TB;
        size_t offB = (size_t)(blockIdx.x * 32 + kc) * TB;
        MBARRIER_EXPECT_TX(mb, 2 * TB);
        CP_BULK(s0,      pAh + offA, TB, mb);
        CP_BULK(s0 + TB, pBh + offB, TB, mb);
    };

    if (tid == 0) {
        issue(0, 0);
        issue(1, 1);
    }

    const int g = lane >> 3, lr = lane & 7;
    const uint32_t arow = (uint32_t)(mbase + lr + ((g & 1) << 3));
    const uint32_t brow = (uint32_t)(nbase + lr + ((g >> 1) << 3));
    const uint32_t aswz = arow & 7, bswz = brow & 7;

    for (int kc = 0; kc < 32; kc++) {
        const int st = kc & 1;
        MBARRIER_WAIT_PARITY(mb0 + st * 8, (kc >> 1) & 1);

        const uint32_t uAh = sb + st * STB8;
        const uint32_t uBh = uAh + TB;

#pragma unroll
        for (int s = 0; s < 4; s++) {
            uint32_t c8a = (uint32_t)(s * 2 + (g >> 1));
            uint32_t c8b = (uint32_t)(s * 2 + (g & 1));
            uint32_t aoff = arow * 128 + ((c8a ^ aswz) << 4);
            uint32_t boff = brow * 128 + ((c8b ^ bswz) << 4);

            uint32_t ah[4][4];
#pragma unroll
            for (int mi = 0; mi < 4; mi++)
                ldsm_x4(ah[mi][0], ah[mi][1], ah[mi][2], ah[mi][3],
                        uAh + aoff + mi * 2048);
            uint32_t bhh[8];
            ldsm_x4(bhh[0], bhh[1], bhh[2], bhh[3], uBh + boff);
            ldsm_x4(bhh[4], bhh[5], bhh[6], bhh[7], uBh + boff + 2048);

#pragma unroll
            for (int mi = 0; mi < 4; mi++)
#pragma unroll
                for (int ni = 0; ni < 4; ni++)
                    mma_f16(acc[mi][ni], ah[mi], bhh[ni * 2], bhh[ni * 2 + 1]);
        }
        __syncthreads();
        if (kc + 2 < 32 && tid == 0) {
            FENCE_PROXY_ASYNC();
            issue(st, kc + 2);
        }
    }

    const int gid = lane >> 2, tig = lane & 3;
    const int rowA = blockIdx.y * 128 + mbase + gid;
    const int colA = blockIdx.x * 128 + nbase + tig * 2;
#pragma unroll
    for (int mi = 0; mi < 4; mi++) {
#pragma unroll
        for (int ni = 0; ni < 4; ni++) {
            float* c0 = C + (size_t)(rowA + mi * 16) * Nn + colA + ni * 8;
            float* c1 = C + (size_t)(rowA + mi * 16 + 8) * Nn + colA + ni * 8;
            c0[0] = acc[mi][ni][0];
            c0[1] = acc[mi][ni][1];
            c1[0] = acc[mi][ni][2];
            c1[1] = acc[mi][ni][3];
        }
    }
}

// ===========================================================================
// attn3: flash attention, single-fp16-MMA QK^T and PV.
// Q(hi) loaded once; K/V(hi) double-buffered via cp.async.bulk.
// SMEM: Qh 32K | stage0 {K 32K, V 32K} | stage1 {K 32K, V 32K} = 160K.
// Output: plain fp16 O (hi only) in tiled layout for gemm8.
// ===========================================================================
#define ATT3_SMEM (10 * TB + 64)   // 163904

__global__ __launch_bounds__(256, 1) void attn3(
    const __half* __restrict__ qh, const __half* __restrict__ kh,
    const __half* __restrict__ vh, __half* __restrict__ oh) {
    extern __shared__ char smc[];
    const uint32_t sb = smem_u32(smc);
    const uint32_t uQh = sb;
    const uint32_t mbQ = sb + 10 * TB;        // +0: Q, +8: st0, +16: st1

    const int bh = blockIdx.y;
    const int b = bh >> 4, h = bh & 15;
    const int qt = blockIdx.x;
    const int tid = threadIdx.x;
    const int warp = tid >> 5, lane = tid & 31;
    const int g8 = lane >> 3, lr = lane & 7;
    const int g4 = lane >> 2, t4 = lane & 3;

    if (tid == 0) {
        MBARRIER_INIT(mbQ, 1);
        MBARRIER_INIT(mbQ + 8, 1);
        MBARRIER_INIT(mbQ + 16, 1);
    }
    __syncthreads();

    auto issueKV = [&](int st, int kt) {
        uint32_t s0 = sb + 2 * TB + st * (4 * TB);
        uint32_t mb = mbQ + 8 + st * 8;
        size_t off = (size_t)((b * 16 + kt) * 32 + 2 * h) * TB;
        MBARRIER_EXPECT_TX(mb, 4 * TB);
        CP_BULK(s0,          (const char*)kh + off, 2 * TB, mb);
        CP_BULK(s0 + 2 * TB, (const char*)vh + off, 2 * TB, mb);
    };

    if (tid == 0) {
        size_t qoff = (size_t)((b * 16 + qt) * 32 + 2 * h) * TB;
        MBARRIER_EXPECT_TX(mbQ, 2 * TB);
        CP_BULK(uQh, (const char*)qh + qoff, 2 * TB, mbQ);
        issueKV(0, 0);
        issueKV(1, 1);
    }

    float accO[16][4];
#pragma unroll
    for (int nd = 0; nd < 16; nd++)
#pragma unroll
        for (int e = 0; e < 4; e++) accO[nd][e] = 0.0f;
    float m0 = -1e30f, m1 = -1e30f, l0 = 0.0f, l1 = 0.0f;

    const uint32_t arow = (uint32_t)(warp * 16 + lr + ((g8 & 1) << 3));
    const uint32_t ulr = (uint32_t)lr;

    MBARRIER_WAIT_PARITY(mbQ, 0);

    for (int kt = 0; kt < 16; kt++) {
        const int st = kt & 1;
        MBARRIER_WAIT_PARITY(mbQ + 8 + st * 8, (kt >> 1) & 1);
        const uint32_t uK = sb + 2 * TB + st * (4 * TB);
        const uint32_t uV = uK + 2 * TB;

        // ---- S = Q K^T ----
        float acc[16][4];
#pragma unroll
        for (int nt = 0; nt < 16; nt++)
#pragma unroll
            for (int e = 0; e < 4; e++) acc[nt][e] = 0.0f;

#pragma unroll
        for (int blk = 0; blk < 2; blk++) {
            const uint32_t uQhb = uQh + blk * TB;
            const uint32_t uKb = uK + blk * TB;
#pragma unroll
            for (int s = 0; s < 4; s++) {
                uint32_t c8a = (uint32_t)(s * 2 + (g8 >> 1));
                uint32_t aoff = arow * 128 + ((c8a ^ ulr) << 4);
                uint32_t qhh[4];
                ldsm_x4(qhh[0], qhh[1], qhh[2], qhh[3], uQhb + aoff);
                uint32_t c8b = (uint32_t)(s * 2 + (g8 & 1));
                uint32_t bcol = (c8b ^ ulr) << 4;
#pragma unroll
                for (int np = 0; np < 8; np++) {
                    uint32_t brow = (uint32_t)(np * 16 + lr + ((g8 >> 1) << 3));
                    uint32_t kf[4];
                    ldsm_x4(kf[0], kf[1], kf[2], kf[3], uKb + brow * 128 + bcol);
                    mma_f16(acc[2 * np],     qhh, kf[0], kf[1]);
                    mma_f16(acc[2 * np + 1], qhh, kf[2], kf[3]);
                }
            }
        }

        // ---- Online softmax ----
        float mx0 = -1e30f, mx1 = -1e30f;
#pragma unroll
        for (int nt = 0; nt < 16; nt++) {
            mx0 = fmaxf(mx0, fmaxf(acc[nt][0], acc[nt][1]));
            mx1 = fmaxf(mx1, fmaxf(acc[nt][2], acc[nt][3]));
        }
        mx0 = fmaxf(mx0, __shfl_xor_sync(0xFFFFFFFFu, mx0, 1));
        mx0 = fmaxf(mx0, __shfl_xor_sync(0xFFFFFFFFu, mx0, 2));
        mx1 = fmaxf(mx1, __shfl_xor_sync(0xFFFFFFFFu, mx1, 1));
        mx1 = fmaxf(mx1, __shfl_xor_sync(0xFFFFFFFFu, mx1, 2));
        float mn0 = fmaxf(m0, mx0), mn1 = fmaxf(m1, mx1);
        float corr0 = exp2p((m0 - mn0) * LOG2E);
        float corr1 = exp2p((m1 - mn1) * LOG2E);
        m0 = mn0; m1 = mn1;

        float sum0 = 0.0f, sum1 = 0.0f;
#pragma unroll
        for (int nt = 0; nt < 16; nt++) {
            acc[nt][0] = exp2p((acc[nt][0] - mn0) * LOG2E);
            acc[nt][1] = exp2p((acc[nt][1] - mn0) * LOG2E);
            acc[nt][2] = exp2p((acc[nt][2] - mn1) * LOG2E);
            acc[nt][3] = exp2p((acc[nt][3] - mn1) * LOG2E);
            sum0 += acc[nt][0] + acc[nt][1];
            sum1 += acc[nt][2] + acc[nt][3];
        }
        sum0 += __shfl_xor_sync(0xFFFFFFFFu, sum0, 1);
        sum0 += __shfl_xor_sync(0xFFFFFFFFu, sum0, 2);
        sum1 += __shfl_xor_sync(0xFFFFFFFFu, sum1, 1);
        sum1 += __shfl_xor_sync(0xFFFFFFFFu, sum1, 2);
        l0 = l0 * corr0 + sum0;
        l1 = l1 * corr1 + sum1;

#pragma unroll
        for (int nd = 0; nd < 16; nd++) {
            accO[nd][0] *= corr0; accO[nd][1] *= corr0;
            accO[nd][2] *= corr1; accO[nd][3] *= corr1;
        }

        // ---- O += P V (P packed to fp16, single MMA) ----
#pragma unroll
        for (int kk = 0; kk < 8; kk++) {
            uint32_t pah[4];
            {
                int n0 = 2 * kk, n1 = 2 * kk + 1;
                pah[0] = pack2h(acc[n0][0], acc[n0][1]);
                pah[1] = pack2h(acc[n0][2], acc[n0][3]);
                pah[2] = pack2h(acc[n1][0], acc[n1][1]);
                pah[3] = pack2h(acc[n1][2], acc[n1][3]);
            }
            uint32_t vrow = (uint32_t)(kk * 16 + lr + ((g8 & 1) << 3));
#pragma unroll
            for (int half = 0; half < 2; half++) {
                uint32_t vf[4][4];
#pragma unroll
                for (int j = 0; j < 4; j++) {
                    uint32_t ndp = (uint32_t)(half * 4 + j);
                    uint32_t blkv = ndp >> 2;
                    uint32_t c8v = (ndp & 3) * 2 + (uint32_t)(g8 >> 1);
                    uint32_t voff = blkv * TB + vrow * 128 + ((c8v ^ ulr) << 4);
                    ldsm_x4_t(vf[j][0], vf[j][1], vf[j][2], vf[j][3], uV + voff);
                }
#pragma unroll
                for (int j = 0; j < 4; j++) {
                    int nda = (half * 4 + j) * 2, ndb = nda + 1;
                    mma_f16(accO[nda], pah, vf[j][0], vf[j][1]);
                    mma_f16(accO[ndb], pah, vf[j][2], vf[j][3]);
                }
            }
        }

        __syncthreads();
        if (kt + 2 < 16 && tid == 0) {
            FENCE_PROXY_ASYNC();
            issueKV(st, kt + 2);
        }
    }

    // ---- Epilogue: normalize, write fp16 TILED layout (hi only) ----
    float inv0 = 1.0f / l0, inv1 = 1.0f / l1;
    const int mrow0 = b * N_SZ + qt * 128 + warp * 16 + g4;   // row1 = +8
    const int panel = mrow0 >> 7;
    const int r0 = mrow0 & 127;
    const uint32_t rsw = (uint32_t)(r0 & 7);
#pragma unroll
    for (int nd = 0; nd < 16; nd++) {
        int kchunk = h * 2 + (nd >> 3);
        uint32_t c8 = (uint32_t)(nd & 7);
        size_t blk = (size_t)(panel * 32 + kchunk) * TB;
        uint32_t in0 = (uint32_t)(r0 * 128) + ((c8 ^ rsw) << 4) + t4 * 4;
        *(uint32_t*)((char*)oh + blk + in0) =
            pack2h(accO[nd][0] * inv0, accO[nd][1] * inv0);
        *(uint32_t*)((char*)oh + blk + in0 + 1024) =
            pack2h(accO[nd][2] * inv1, accO[nd][3] * inv1);
    }
}

// ---------------------------------------------------------------------------
// Launch
// ---------------------------------------------------------------------------
extern "C" void kernel_launch(void* const* d_in, const int* in_sizes, int n_in,
                              void* d_out, int out_size) {
    const float* x  = (const float*)d_in[0];
    const float* Wq = (const float*)d_in[1];
    const float* Wk = (const float*)d_in[2];
    const float* Wv = (const float*)d_in[3];
    const float* Wo = (const float*)d_in[4];
    float* out = (float*)d_out;

    float *q_ptr, *k_ptr, *v_ptr;
    __half *xh, *xl, *wh, *oh, *qhp, *khp, *vhp;
    cudaGetSymbolAddress((void**)&q_ptr, g_q);
    cudaGetSymbolAddress((void**)&k_ptr, g_k);
    cudaGetSymbolAddress((void**)&v_ptr, g_v);
    cudaGetSymbolAddress((void**)&xh, g_xh);
    cudaGetSymbolAddress((void**)&xl, g_xl);
    cudaGetSymbolAddress((void**)&wh, g_wh);
    cudaGetSymbolAddress((void**)&oh, g_oh);
    cudaGetSymbolAddress((void**)&qhp, g_qh);
    cudaGetSymbolAddress((void**)&khp, g_kh);
    cudaGetSymbolAddress((void**)&vhp, g_vh);

    cudaFuncSetAttribute(gemm7, cudaFuncAttributeMaxDynamicSharedMemorySize,
                         G7_SMEM);
    cudaFuncSetAttribute(gemm8, cudaFuncAttributeMaxDynamicSharedMemorySize,
                         G8_SMEM);
    cudaFuncSetAttribute(attn3, cudaFuncAttributeMaxDynamicSharedMemorySize,
                         ATT3_SMEM);

    const size_t woff = (size_t)D_SZ * D_SZ;

    // Pre-split + tile operands (x: hi+lo; weights: hi only, fused launch)
    split_tiled<<<M_SZ, 256>>>(x, xh, xl, M_SZ);
    dim3 gw(D_SZ, 4);
    split_tiled_w<<<gw, 256>>>(Wq, Wk, Wv, Wo, wh);

    // Fused Q/K/V projection
    dim3 gq(D_SZ / 128, M_SZ / 128, 3);    // (16, 32, 3)
    gemm7<<<gq, 256, G7_SMEM>>>(xh, xl, wh, q_ptr, k_ptr, v_ptr, D_SZ);

    // RoPE + convert to tiled fp16 (Q hi scaled, K hi, V hi)
    rope_convert<<<(M_SZ * H_SZ * 8) / 256, 256>>>(q_ptr, k_ptr, v_ptr,
                                                   qhp, khp, vhp);

    dim3 ga(N_SZ / 128, B_SZ * H_SZ);      // (16, 32)
    attn3<<<ga, 256, ATT3_SMEM>>>(qhp, khp, vhp, oh);

    // O projection (single-MMA, A = O hi)
    dim3 go(D_SZ / 128, M_SZ / 128, 1);
    gemm8<<<go, 256, G8_SMEM>>>(oh, wh + 3 * woff, out, D_SZ);
}

// round 17
// speedup vs baseline: 1.6490x; 1.6490x over previous
#include <cuda_runtime.h>
#include <cuda_fp16.h>
#include <cstdint>

#define B_SZ 2
#define N_SZ 2048
#define D_SZ 2048
#define H_SZ 16
#define HD_SZ 128
#define M_SZ (B_SZ * N_SZ)   // 4096

// Tiled operand layout: 16KB blocks [128 rows x 64 cols f16], row stride
// 128 B, 16B-group swizzle c8 ^= (r & 7). Block id = panel*32 + kchunk.
#define TB 16384

// Scratch (static device arrays; no allocation allowed)
__device__ float g_q[M_SZ * D_SZ];
__device__ float g_k[M_SZ * D_SZ];
__device__ float g_v[M_SZ * D_SZ];
__device__ __align__(128) __half g_xh[M_SZ * D_SZ];
__device__ __align__(128) __half g_xl[M_SZ * D_SZ];
__device__ __align__(128) __half g_wh[4 * D_SZ * D_SZ];
__device__ __align__(128) __half g_oh[M_SZ * D_SZ];
__device__ __align__(128) __half g_qh[M_SZ * D_SZ];
__device__ __align__(128) __half g_kh[M_SZ * D_SZ];
__device__ __align__(128) __half g_vh[M_SZ * D_SZ];

// ===========================================================================
// PTX helpers (sm_80/sm_90 base-arch: legal at compute_103)
// ===========================================================================
__device__ __forceinline__ uint32_t smem_u32(const void* p) {
    uint32_t a;
    asm("{ .reg .u64 t; cvta.to.shared.u64 t, %1; cvt.u32.u64 %0, t; }"
        : "=r"(a) : "l"(p));
    return a;
}

__device__ __forceinline__ void ldsm_x4(uint32_t& r0, uint32_t& r1,
                                        uint32_t& r2, uint32_t& r3,
                                        uint32_t addr) {
    asm volatile("ldmatrix.sync.aligned.m8n8.x4.shared.b16 {%0,%1,%2,%3}, [%4];"
                 : "=r"(r0), "=r"(r1), "=r"(r2), "=r"(r3) : "r"(addr));
}

__device__ __forceinline__ void ldsm_x4_t(uint32_t& r0, uint32_t& r1,
                                          uint32_t& r2, uint32_t& r3,
                                          uint32_t addr) {
    asm volatile("ldmatrix.sync.aligned.m8n8.x4.trans.shared.b16 {%0,%1,%2,%3}, [%4];"
                 : "=r"(r0), "=r"(r1), "=r"(r2), "=r"(r3) : "r"(addr));
}

__device__ __forceinline__ void mma_f16(float* d, const uint32_t* a,
                                        uint32_t b0, uint32_t b1) {
    asm volatile(
        "mma.sync.aligned.m16n8k16.row.col.f32.f16.f16.f32 "
        "{%0,%1,%2,%3}, {%4,%5,%6,%7}, {%8,%9}, {%0,%1,%2,%3};"
        : "+f"(d[0]), "+f"(d[1]), "+f"(d[2]), "+f"(d[3])
        : "r"(a[0]), "r"(a[1]), "r"(a[2]), "r"(a[3]), "r"(b0), "r"(b1));
}

// Non-tensor bulk TMA: contiguous global -> contiguous shared
#define CP_BULK(saddr, gptr, bytes, mbar) \
    asm volatile( \
        "cp.async.bulk.shared::cta.global.mbarrier::complete_tx::bytes " \
        "[%0], [%1], %2, [%3];" \
        :: "r"(saddr), "l"(gptr), "r"(bytes), "r"(mbar) : "memory")

#define MBARRIER_INIT(mbar, count) \
    asm volatile("mbarrier.init.shared.b64 [%0], %1;" \
                 :: "r"(mbar), "r"((uint32_t)(count)) : "memory")

#define MBARRIER_EXPECT_TX(mbar, bytes) \
    asm volatile("mbarrier.arrive.expect_tx.shared.b64 _, [%0], %1;" \
                 :: "r"(mbar), "r"((uint32_t)(bytes)) : "memory")

#define MBARRIER_WAIT_PARITY(mbar, parity) do { \
    uint32_t _mb = (mbar); \
    uint32_t _ph = (parity); \
    asm volatile( \
        "{\n\t" \
        ".reg .pred P1;\n\t" \
        "WAIT_LOOP_%=:\n\t" \
        "mbarrier.try_wait.parity.acquire.cta.shared::cta.b64 P1, [%0], %1, 0x989680;\n\t" \
        "@P1 bra.uni WAIT_DONE_%=;\n\t" \
        "bra.uni WAIT_LOOP_%=;\n\t" \
        "WAIT_DONE_%=:\n\t" \
        "}" \
        :: "r"(_mb), "r"(_ph) : "memory"); \
} while (0)

#define FENCE_PROXY_ASYNC() \
    asm volatile("fence.proxy.async.shared::cta;" ::: "memory")

// pack two fp32 -> f16x2 (e0 low, e1 high)
__device__ __forceinline__ uint32_t pack2h(float e0, float e1) {
    __half2 h = __floats2half2_rn(e0, e1);
    return *(uint32_t*)&h;
}

__device__ __forceinline__ void split2h(float e0, float e1,
                                        uint32_t& h, uint32_t& l) {
    h = pack2h(e0, e1);
    __half2 hh = *(__half2*)&h;
    l = pack2h(e0 - __low2float(hh), e1 - __high2float(hh));
}

__device__ __forceinline__ void split4h(float4 f, uint2& hi, uint2& lo) {
    split2h(f.x, f.y, hi.x, lo.x);
    split2h(f.z, f.w, hi.y, lo.y);
}

// Fast exp2 on the FMA pipe
__device__ __forceinline__ float exp2p(float y) {
    y = fmaxf(y, -126.0f);
    int n = __float2int_rd(y);
    float f = y - (float)n;
    float r = 1.8775767e-3f;
    r = fmaf(r, f, 8.9893397e-3f);
    r = fmaf(r, f, 5.5826318e-2f);
    r = fmaf(r, f, 2.4015361e-1f);
    r = fmaf(r, f, 6.9315308e-1f);
    r = fmaf(r, f, 1.0f);
    return r * __int_as_float((n + 127) << 23);
}

#define LOG2E 1.4426950408889634f

// ===========================================================================
// Split kernels: fp32 [nrows x 2048] -> tiled/swizzled fp16
// ===========================================================================
__global__ __launch_bounds__(256) void split_tiled(
    const float* __restrict__ src, __half* __restrict__ hi,
    __half* __restrict__ lo, int nrows) {
    int idx = blockIdx.x * 256 + threadIdx.x;
    if (idx >= nrows * 256) return;
    int rg = idx >> 8;
    int g = idx & 255;
    int kc = g >> 3, c8 = g & 7;
    int panel = rg >> 7, r = rg & 127;

    const float4* s = (const float4*)(src + (size_t)rg * 2048 + kc * 64 + c8 * 8);
    float4 f0 = s[0], f1 = s[1];
    uint2 h0, l0, h1, l1;
    split4h(f0, h0, l0);
    split4h(f1, h1, l1);

    size_t off = (size_t)(panel * 32 + kc) * TB
               + (uint32_t)(r * 128 + ((c8 ^ (r & 7)) << 4));
    *(uint4*)((char*)hi + off) = make_uint4(h0.x, h0.y, h1.x, h1.y);
    *(uint4*)((char*)lo + off) = make_uint4(l0.x, l0.y, l1.x, l1.y);
}

// All four weights in one launch: blockIdx.y selects src / dst slice.
__global__ __launch_bounds__(256) void split_tiled_w(
    const float* __restrict__ w0, const float* __restrict__ w1,
    const float* __restrict__ w2, const float* __restrict__ w3,
    __half* __restrict__ hi) {
    int idx = blockIdx.x * 256 + threadIdx.x;
    int wz = blockIdx.y;
    const float* src = (wz == 0) ? w0 : (wz == 1) ? w1 : (wz == 2) ? w2 : w3;
    int rg = idx >> 8;
    int g = idx & 255;
    int kc = g >> 3, c8 = g & 7;
    int panel = rg >> 7, r = rg & 127;

    const float4* s = (const float4*)(src + (size_t)rg * 2048 + kc * 64 + c8 * 8);
    float4 f0 = s[0], f1 = s[1];

    size_t off = (size_t)wz * (D_SZ * D_SZ) * 2
               + (size_t)(panel * 32 + kc) * TB
               + (uint32_t)(r * 128 + ((c8 ^ (r & 7)) << 4));
    *(uint4*)((char*)hi + off) = make_uint4(pack2h(f0.x, f0.y), pack2h(f0.z, f0.w),
                                            pack2h(f1.x, f1.y), pack2h(f1.z, f1.w));
}

// ===========================================================================
// rope_convert: read fp32 q/k/v, apply RoPE to q/k (+1/sqrt(d) scale on q),
// write tiled/swizzled fp16: Q hi, K hi, V hi.
// ===========================================================================
__global__ __launch_bounds__(256) void rope_convert(
    const float* __restrict__ q, const float* __restrict__ k,
    const float* __restrict__ v,
    __half* __restrict__ qh, __half* __restrict__ kh, __half* __restrict__ vh) {
    int idx = blockIdx.x * 256 + threadIdx.x;     // M*16*8 = 524288
    int rg = idx >> 7;
    int rem = idx & 127;
    int h = rem >> 3, c8 = rem & 7;
    int pos = rg & (N_SZ - 1);
    int panel = rg >> 7, r = rg & 127;
    const float sc = 0.08838834764831845f;

    float cc[8], ss[8];
#pragma unroll
    for (int e = 0; e < 8; e++) {
        int i = c8 * 8 + e;
        float inv_freq = powf(10000.0f, -(float)i * (1.0f / 64.0f));
        sincosf((float)pos * inv_freq, &ss[e], &cc[e]);
    }

    size_t base = (size_t)rg * D_SZ + h * HD_SZ + c8 * 8;
    float q1[8], q2[8], k1[8], k2[8], v1[8], v2[8];
    *(float4*)&q1[0] = *(const float4*)(q + base);
    *(float4*)&q1[4] = *(const float4*)(q + base + 4);
    *(float4*)&q2[0] = *(const float4*)(q + base + 64);
    *(float4*)&q2[4] = *(const float4*)(q + base + 68);
    *(float4*)&k1[0] = *(const float4*)(k + base);
    *(float4*)&k1[4] = *(const float4*)(k + base + 4);
    *(float4*)&k2[0] = *(const float4*)(k + base + 64);
    *(float4*)&k2[4] = *(const float4*)(k + base + 68);
    *(float4*)&v1[0] = *(const float4*)(v + base);
    *(float4*)&v1[4] = *(const float4*)(v + base + 4);
    *(float4*)&v2[0] = *(const float4*)(v + base + 64);
    *(float4*)&v2[4] = *(const float4*)(v + base + 68);

    float qo1[8], qo2[8], ko1[8], ko2[8];
#pragma unroll
    for (int e = 0; e < 8; e++) {
        qo1[e] = (q1[e] * cc[e] - q2[e] * ss[e]) * sc;
        qo2[e] = (q2[e] * cc[e] + q1[e] * ss[e]) * sc;
        ko1[e] = k1[e] * cc[e] - k2[e] * ss[e];
        ko2[e] = k2[e] * cc[e] + k1[e] * ss[e];
    }

    uint32_t inoff = (uint32_t)(r * 128 + ((c8 ^ (r & 7)) << 4));
    size_t b0 = (size_t)(panel * 32 + 2 * h) * TB + inoff;
    size_t b1 = b0 + TB;

    *(uint4*)((char*)qh + b0) = make_uint4(pack2h(qo1[0], qo1[1]), pack2h(qo1[2], qo1[3]),
                                           pack2h(qo1[4], qo1[5]), pack2h(qo1[6], qo1[7]));
    *(uint4*)((char*)qh + b1) = make_uint4(pack2h(qo2[0], qo2[1]), pack2h(qo2[2], qo2[3]),
                                           pack2h(qo2[4], qo2[5]), pack2h(qo2[6], qo2[7]));
    *(uint4*)((char*)kh + b0) = make_uint4(pack2h(ko1[0], ko1[1]), pack2h(ko1[2], ko1[3]),
                                           pack2h(ko1[4], ko1[5]), pack2h(ko1[6], ko1[7]));
    *(uint4*)((char*)kh + b1) = make_uint4(pack2h(ko2[0], ko2[1]), pack2h(ko2[2], ko2[3]),
                                           pack2h(ko2[4], ko2[5]), pack2h(ko2[6], ko2[7]));
    *(uint4*)((char*)vh + b0) = make_uint4(pack2h(v1[0], v1[1]), pack2h(v1[2], v1[3]),
                                           pack2h(v1[4], v1[5]), pack2h(v1[6], v1[7]));
    *(uint4*)((char*)vh + b1) = make_uint4(pack2h(v2[0], v2[1]), pack2h(v2[2], v2[3]),
                                           pack2h(v2[4], v2[5]), pack2h(v2[6], v2[7]));
}

// ===========================================================================
// gemm7: C[M,Nn] = A @ W^T, fp16 2-MMA (A = hi+lo, W = hi). cp.async.bulk,
// 2-stage (96KB smem) -> 2 CTAs/SM. Used for Q/K/V projections.
// ===========================================================================
#define STB7   (3 * TB)
#define G7_MBAR (2 * STB7)
#define G7_SMEM (2 * STB7 + 32)    // 98336

__global__ __launch_bounds__(256, 2) void gemm7(
    const __half* __restrict__ Ah, const __half* __restrict__ Al,
    const __half* __restrict__ Wh,
    float* __restrict__ C0, float* __restrict__ C1, float* __restrict__ C2,
    int Nn) {
    extern __shared__ char dsm[];
    const uint32_t sb = smem_u32(dsm);

    const int tid = threadIdx.x;
    const int warp = tid >> 5;
    const int lane = tid & 31;
    const int mbase = (warp >> 2) * 64;
    const int nbase = (warp & 3) * 32;

    const int z = blockIdx.z;
    float* C = (z == 0) ? C0 : (z == 1) ? C1 : C2;
    const char* pAh = (const char*)Ah;
    const char* pAl = (const char*)Al;
    const char* pBh = (const char*)(Wh + (size_t)z * D_SZ * D_SZ);

    float acc[4][4][4];
#pragma unroll
    for (int i = 0; i < 4; i++)
#pragma unroll
        for (int j = 0; j < 4; j++)
#pragma unroll
            for (int e = 0; e < 4; e++) acc[i][j][e] = 0.0f;

    const uint32_t mb0 = sb + G7_MBAR;

    if (tid == 0) {
        MBARRIER_INIT(mb0, 1);
        MBARRIER_INIT(mb0 + 8, 1);
    }
    __syncthreads();

    auto issue = [&](int st, int kc) {
        uint32_t s0 = sb + st * STB7;
        uint32_t mb = mb0 + st * 8;
        size_t offA = (size_t)(blockIdx.y * 32 + kc) * TB;
        size_t offB = (size_t)(blockIdx.x * 32 + kc) * TB;
        MBARRIER_EXPECT_TX(mb, 3 * TB);
        CP_BULK(s0,          pAh + offA, TB, mb);
        CP_BULK(s0 + TB,     pAl + offA, TB, mb);
        CP_BULK(s0 + 2 * TB, pBh + offB, TB, mb);
    };

    if (tid == 0) {
        issue(0, 0);
        issue(1, 1);
    }

    const int g = lane >> 3, lr = lane & 7;
    const uint32_t arow = (uint32_t)(mbase + lr + ((g & 1) << 3));
    const uint32_t brow = (uint32_t)(nbase + lr + ((g >> 1) << 3));
    const uint32_t aswz = arow & 7, bswz = brow & 7;

    for (int kc = 0; kc < 32; kc++) {
        const int st = kc & 1;
        MBARRIER_WAIT_PARITY(mb0 + st * 8, (kc >> 1) & 1);

        const uint32_t uAh = sb + st * STB7;
        const uint32_t uAl = uAh + TB;
        const uint32_t uBh = uAh + 2 * TB;

#pragma unroll
        for (int s = 0; s < 4; s++) {
            uint32_t c8a = (uint32_t)(s * 2 + (g >> 1));
            uint32_t c8b = (uint32_t)(s * 2 + (g & 1));
            uint32_t aoff = arow * 128 + ((c8a ^ aswz) << 4);
            uint32_t boff = brow * 128 + ((c8b ^ bswz) << 4);

            uint32_t ah[4][4], al[4][4];
#pragma unroll
            for (int mi = 0; mi < 4; mi++) {
                ldsm_x4(ah[mi][0], ah[mi][1], ah[mi][2], ah[mi][3],
                        uAh + aoff + mi * 2048);
                ldsm_x4(al[mi][0], al[mi][1], al[mi][2], al[mi][3],
                        uAl + aoff + mi * 2048);
            }
            uint32_t bh[8];
            ldsm_x4(bh[0], bh[1], bh[2], bh[3], uBh + boff);
            ldsm_x4(bh[4], bh[5], bh[6], bh[7], uBh + boff + 2048);

#pragma unroll
            for (int mi = 0; mi < 4; mi++) {
#pragma unroll
                for (int ni = 0; ni < 4; ni++) {
                    mma_f16(acc[mi][ni], ah[mi], bh[ni * 2], bh[ni * 2 + 1]);
                    mma_f16(acc[mi][ni], al[mi], bh[ni * 2], bh[ni * 2 + 1]);
                }
            }
        }
        __syncthreads();
        if (kc + 2 < 32 && tid == 0) {
            FENCE_PROXY_ASYNC();
            issue(st, kc + 2);
        }
    }

    const int gid = lane >> 2, tig = lane & 3;
    const int rowA = blockIdx.y * 128 + mbase + gid;
    const int colA = blockIdx.x * 128 + nbase + tig * 2;
#pragma unroll
    for (int mi = 0; mi < 4; mi++) {
#pragma unroll
        for (int ni = 0; ni < 4; ni++) {
            float* c0 = C + (size_t)(rowA + mi * 16) * Nn + colA + ni * 8;
            float* c1 = C + (size_t)(rowA + mi * 16 + 8) * Nn + colA + ni * 8;
            c0[0] = acc[mi][ni][0];
            c0[1] = acc[mi][ni][1];
            c1[0] = acc[mi][ni][2];
            c1[1] = acc[mi][ni][3];
        }
    }
}

// ===========================================================================
// gemm8: single-MMA GEMM (A = hi only, W = hi). 2-stage 64KB smem.
// __launch_bounds__(256, 2): 128-reg cap (needs ~110; the (256,3) variant
// capped at 84 regs and SPILLED accumulators into the mainloop).
// ===========================================================================
#define STB8   (2 * TB)
#define G8_MBAR (2 * STB8)
#define G8_SMEM (2 * STB8 + 32)    // 65568

__global__ __launch_bounds__(256, 2) void gemm8(
    const __half* __restrict__ Ah, const __half* __restrict__ Wh,
    float* __restrict__ C, int Nn) {
    extern __shared__ char dsm[];
    const uint32_t sb = smem_u32(dsm);

    const int tid = threadIdx.x;
    const int warp = tid >> 5;
    const int lane = tid & 31;
    const int mbase = (warp >> 2) * 64;
    const int nbase = (warp & 3) * 32;

    const char* pAh = (const char*)Ah;
    const char* pBh = (const char*)Wh;

    float acc[4][4][4];
#pragma unroll
    for (int i = 0; i < 4; i++)
#pragma unroll
        for (int j = 0; j < 4; j++)
#pragma unroll
            for (int e = 0; e < 4; e++) acc[i][j][e] = 0.0f;

    const uint32_t mb0 = sb + G8_MBAR;

    if (tid == 0) {
        MBARRIER_INIT(mb0, 1);
        MBARRIER_INIT(mb0 + 8, 1);
    }
    __syncthreads();

    auto issue = [&](int st, int kc) {
        uint32_t s0 = sb + st * STB8;
        uint32_t mb = mb0 + st * 8;
        size_t offA = (size_t)(blockIdx.y * 32 + kc) * TB;
        size_t offB = (size_t)(blockIdx.x * 32 + kc) * TB;
        MBARRIER_EXPECT_TX(mb, 2 * TB);
        CP_BULK(s0,      pAh + offA, TB, mb);
        CP_BULK(s0 + TB, pBh + offB, TB, mb);
    };

    if (tid == 0) {
        issue(0, 0);
        issue(1, 1);
    }

    const int g = lane >> 3, lr = lane & 7;
    const uint32_t arow = (uint32_t)(mbase + lr + ((g & 1) << 3));
    const uint32_t brow = (uint32_t)(nbase + lr + ((g >> 1) << 3));
    const uint32_t aswz = arow & 7, bswz = brow & 7;

    for (int kc = 0; kc < 32; kc++) {
        const int st = kc & 1;
        MBARRIER_WAIT_PARITY(mb0 + st * 8, (kc >> 1) & 1);

        const uint32_t uAh = sb + st * STB8;
        const uint32_t uBh = uAh + TB;

#pragma unroll
        for (int s = 0; s < 4; s++) {
            uint32_t c8a = (uint32_t)(s * 2 + (g >> 1));
            uint32_t c8b = (uint32_t)(s * 2 + (g & 1));
            uint32_t aoff = arow * 128 + ((c8a ^ aswz) << 4);
            uint32_t boff = brow * 128 + ((c8b ^ bswz) << 4);

            uint32_t ah[4][4];
#pragma unroll
            for (int mi = 0; mi < 4; mi++)
                ldsm_x4(ah[mi][0], ah[mi][1], ah[mi][2], ah[mi][3],
                        uAh + aoff + mi * 2048);
            uint32_t bhh[8];
            ldsm_x4(bhh[0], bhh[1], bhh[2], bhh[3], uBh + boff);
            ldsm_x4(bhh[4], bhh[5], bhh[6], bhh[7], uBh + boff + 2048);

#pragma unroll
            for (int mi = 0; mi < 4; mi++)
#pragma unroll
                for (int ni = 0; ni < 4; ni++)
                    mma_f16(acc[mi][ni], ah[mi], bhh[ni * 2], bhh[ni * 2 + 1]);
        }
        __syncthreads();
        if (kc + 2 < 32 && tid == 0) {
            FENCE_PROXY_ASYNC();
            issue(st, kc + 2);
        }
    }

    const int gid = lane >> 2, tig = lane & 3;
    const int rowA = blockIdx.y * 128 + mbase + gid;
    const int colA = blockIdx.x * 128 + nbase + tig * 2;
#pragma unroll
    for (int mi = 0; mi < 4; mi++) {
#pragma unroll
        for (int ni = 0; ni < 4; ni++) {
            float* c0 = C + (size_t)(rowA + mi * 16) * Nn + colA + ni * 8;
            float* c1 = C + (size_t)(rowA + mi * 16 + 8) * Nn + colA + ni * 8;
            c0[0] = acc[mi][ni][0];
            c0[1] = acc[mi][ni][1];
            c1[0] = acc[mi][ni][2];
            c1[1] = acc[mi][ni][3];
        }
    }
}

// ===========================================================================
// attn3: flash attention, single-fp16-MMA QK^T and PV.
// Q(hi) loaded once; K/V(hi) double-buffered via cp.async.bulk.
// SMEM: Qh 32K | stage0 {K 32K, V 32K} | stage1 {K 32K, V 32K} = 160K.
// Output: plain fp16 O (hi only) in tiled layout for gemm8.
// ===========================================================================
#define ATT3_SMEM (10 * TB + 64)   // 163904

__global__ __launch_bounds__(256, 1) void attn3(
    const __half* __restrict__ qh, const __half* __restrict__ kh,
    const __half* __restrict__ vh, __half* __restrict__ oh) {
    extern __shared__ char smc[];
    const uint32_t sb = smem_u32(smc);
    const uint32_t uQh = sb;
    const uint32_t mbQ = sb + 10 * TB;        // +0: Q, +8: st0, +16: st1

    const int bh = blockIdx.y;
    const int b = bh >> 4, h = bh & 15;
    const int qt = blockIdx.x;
    const int tid = threadIdx.x;
    const int warp = tid >> 5, lane = tid & 31;
    const int g8 = lane >> 3, lr = lane & 7;
    const int g4 = lane >> 2, t4 = lane & 3;

    if (tid == 0) {
        MBARRIER_INIT(mbQ, 1);
        MBARRIER_INIT(mbQ + 8, 1);
        MBARRIER_INIT(mbQ + 16, 1);
    }
    __syncthreads();

    auto issueKV = [&](int st, int kt) {
        uint32_t s0 = sb + 2 * TB + st * (4 * TB);
        uint32_t mb = mbQ + 8 + st * 8;
        size_t off = (size_t)((b * 16 + kt) * 32 + 2 * h) * TB;
        MBARRIER_EXPECT_TX(mb, 4 * TB);
        CP_BULK(s0,          (const char*)kh + off, 2 * TB, mb);
        CP_BULK(s0 + 2 * TB, (const char*)vh + off, 2 * TB, mb);
    };

    if (tid == 0) {
        size_t qoff = (size_t)((b * 16 + qt) * 32 + 2 * h) * TB;
        MBARRIER_EXPECT_TX(mbQ, 2 * TB);
        CP_BULK(uQh, (const char*)qh + qoff, 2 * TB, mbQ);
        issueKV(0, 0);
        issueKV(1, 1);
    }

    float accO[16][4];
#pragma unroll
    for (int nd = 0; nd < 16; nd++)
#pragma unroll
        for (int e = 0; e < 4; e++) accO[nd][e] = 0.0f;
    float m0 = -1e30f, m1 = -1e30f, l0 = 0.0f, l1 = 0.0f;

    const uint32_t arow = (uint32_t)(warp * 16 + lr + ((g8 & 1) << 3));
    const uint32_t ulr = (uint32_t)lr;

    MBARRIER_WAIT_PARITY(mbQ, 0);

    for (int kt = 0; kt < 16; kt++) {
        const int st = kt & 1;
        MBARRIER_WAIT_PARITY(mbQ + 8 + st * 8, (kt >> 1) & 1);
        const uint32_t uK = sb + 2 * TB + st * (4 * TB);
        const uint32_t uV = uK + 2 * TB;

        // ---- S = Q K^T ----
        float acc[16][4];
#pragma unroll
        for (int nt = 0; nt < 16; nt++)
#pragma unroll
            for (int e = 0; e < 4; e++) acc[nt][e] = 0.0f;

#pragma unroll
        for (int blk = 0; blk < 2; blk++) {
            const uint32_t uQhb = uQh + blk * TB;
            const uint32_t uKb = uK + blk * TB;
#pragma unroll
            for (int s = 0; s < 4; s++) {
                uint32_t c8a = (uint32_t)(s * 2 + (g8 >> 1));
                uint32_t aoff = arow * 128 + ((c8a ^ ulr) << 4);
                uint32_t qhh[4];
                ldsm_x4(qhh[0], qhh[1], qhh[2], qhh[3], uQhb + aoff);
                uint32_t c8b = (uint32_t)(s * 2 + (g8 & 1));
                uint32_t bcol = (c8b ^ ulr) << 4;
#pragma unroll
                for (int np = 0; np < 8; np++) {
                    uint32_t brow = (uint32_t)(np * 16 + lr + ((g8 >> 1) << 3));
                    uint32_t kf[4];
                    ldsm_x4(kf[0], kf[1], kf[2], kf[3], uKb + brow * 128 + bcol);
                    mma_f16(acc[2 * np],     qhh, kf[0], kf[1]);
                    mma_f16(acc[2 * np + 1], qhh, kf[2], kf[3]);
                }
            }
        }

        // ---- Online softmax ----
        float mx0 = -1e30f, mx1 = -1e30f;
#pragma unroll
        for (int nt = 0; nt < 16; nt++) {
            mx0 = fmaxf(mx0, fmaxf(acc[nt][0], acc[nt][1]));
            mx1 = fmaxf(mx1, fmaxf(acc[nt][2], acc[nt][3]));
        }
        mx0 = fmaxf(mx0, __shfl_xor_sync(0xFFFFFFFFu, mx0, 1));
        mx0 = fmaxf(mx0, __shfl_xor_sync(0xFFFFFFFFu, mx0, 2));
        mx1 = fmaxf(mx1, __shfl_xor_sync(0xFFFFFFFFu, mx1, 1));
        mx1 = fmaxf(mx1, __shfl_xor_sync(0xFFFFFFFFu, mx1, 2));
        float mn0 = fmaxf(m0, mx0), mn1 = fmaxf(m1, mx1);
        float corr0 = exp2p((m0 - mn0) * LOG2E);
        float corr1 = exp2p((m1 - mn1) * LOG2E);
        m0 = mn0; m1 = mn1;

        float sum0 = 0.0f, sum1 = 0.0f;
#pragma unroll
        for (int nt = 0; nt < 16; nt++) {
            acc[nt][0] = exp2p((acc[nt][0] - mn0) * LOG2E);
            acc[nt][1] = exp2p((acc[nt][1] - mn0) * LOG2E);
            acc[nt][2] = exp2p((acc[nt][2] - mn1) * LOG2E);
            acc[nt][3] = exp2p((acc[nt][3] - mn1) * LOG2E);
            sum0 += acc[nt][0] + acc[nt][1];
            sum1 += acc[nt][2] + acc[nt][3];
        }
        sum0 += __shfl_xor_sync(0xFFFFFFFFu, sum0, 1);
        sum0 += __shfl_xor_sync(0xFFFFFFFFu, sum0, 2);
        sum1 += __shfl_xor_sync(0xFFFFFFFFu, sum1, 1);
        sum1 += __shfl_xor_sync(0xFFFFFFFFu, sum1, 2);
        l0 = l0 * corr0 + sum0;
        l1 = l1 * corr1 + sum1;

#pragma unroll
        for (int nd = 0; nd < 16; nd++) {
            accO[nd][0] *= corr0; accO[nd][1] *= corr0;
            accO[nd][2] *= corr1; accO[nd][3] *= corr1;
        }

        // ---- O += P V (P packed to fp16, single MMA) ----
#pragma unroll
        for (int kk = 0; kk < 8; kk++) {
            uint32_t pah[4];
            {
                int n0 = 2 * kk, n1 = 2 * kk + 1;
                pah[0] = pack2h(acc[n0][0], acc[n0][1]);
                pah[1] = pack2h(acc[n0][2], acc[n0][3]);
                pah[2] = pack2h(acc[n1][0], acc[n1][1]);
                pah[3] = pack2h(acc[n1][2], acc[n1][3]);
            }
            uint32_t vrow = (uint32_t)(kk * 16 + lr + ((g8 & 1) << 3));
#pragma unroll
            for (int half = 0; half < 2; half++) {
                uint32_t vf[4][4];
#pragma unroll
                for (int j = 0; j < 4; j++) {
                    uint32_t ndp = (uint32_t)(half * 4 + j);
                    uint32_t blkv = ndp >> 2;
                    uint32_t c8v = (ndp & 3) * 2 + (uint32_t)(g8 >> 1);
                    uint32_t voff = blkv * TB + vrow * 128 + ((c8v ^ ulr) << 4);
                    ldsm_x4_t(vf[j][0], vf[j][1], vf[j][2], vf[j][3], uV + voff);
                }
#pragma unroll
                for (int j = 0; j < 4; j++) {
                    int nda = (half * 4 + j) * 2, ndb = nda + 1;
                    mma_f16(accO[nda], pah, vf[j][0], vf[j][1]);
                    mma_f16(accO[ndb], pah, vf[j][2], vf[j][3]);
                }
            }
        }

        __syncthreads();
        if (kt + 2 < 16 && tid == 0) {
            FENCE_PROXY_ASYNC();
            issueKV(st, kt + 2);
        }
    }

    // ---- Epilogue: normalize, write fp16 TILED layout (hi only) ----
    float inv0 = 1.0f / l0, inv1 = 1.0f / l1;
    const int mrow0 = b * N_SZ + qt * 128 + warp * 16 + g4;   // row1 = +8
    const int panel = mrow0 >> 7;
    const int r0 = mrow0 & 127;
    const uint32_t rsw = (uint32_t)(r0 & 7);
#pragma unroll
    for (int nd = 0; nd < 16; nd++) {
        int kchunk = h * 2 + (nd >> 3);
        uint32_t c8 = (uint32_t)(nd & 7);
        size_t blk = (size_t)(panel * 32 + kchunk) * TB;
        uint32_t in0 = (uint32_t)(r0 * 128) + ((c8 ^ rsw) << 4) + t4 * 4;
        *(uint32_t*)((char*)oh + blk + in0) =
            pack2h(accO[nd][0] * inv0, accO[nd][1] * inv0);
        *(uint32_t*)((char*)oh + blk + in0 + 1024) =
            pack2h(accO[nd][2] * inv1, accO[nd][3] * inv1);
    }
}

// ---------------------------------------------------------------------------
// Launch
// ---------------------------------------------------------------------------
extern "C" void kernel_launch(void* const* d_in, const int* in_sizes, int n_in,
                              void* d_out, int out_size) {
    const float* x  = (const float*)d_in[0];
    const float* Wq = (const float*)d_in[1];
    const float* Wk = (const float*)d_in[2];
    const float* Wv = (const float*)d_in[3];
    const float* Wo = (const float*)d_in[4];
    float* out = (float*)d_out;

    float *q_ptr, *k_ptr, *v_ptr;
    __half *xh, *xl, *wh, *oh, *qhp, *khp, *vhp;
    cudaGetSymbolAddress((void**)&q_ptr, g_q);
    cudaGetSymbolAddress((void**)&k_ptr, g_k);
    cudaGetSymbolAddress((void**)&v_ptr, g_v);
    cudaGetSymbolAddress((void**)&xh, g_xh);
    cudaGetSymbolAddress((void**)&xl, g_xl);
    cudaGetSymbolAddress((void**)&wh, g_wh);
    cudaGetSymbolAddress((void**)&oh, g_oh);
    cudaGetSymbolAddress((void**)&qhp, g_qh);
    cudaGetSymbolAddress((void**)&khp, g_kh);
    cudaGetSymbolAddress((void**)&vhp, g_vh);

    cudaFuncSetAttribute(gemm7, cudaFuncAttributeMaxDynamicSharedMemorySize,
                         G7_SMEM);
    cudaFuncSetAttribute(gemm8, cudaFuncAttributeMaxDynamicSharedMemorySize,
                         G8_SMEM);
    cudaFuncSetAttribute(attn3, cudaFuncAttributeMaxDynamicSharedMemorySize,
                         ATT3_SMEM);

    const size_t woff = (size_t)D_SZ * D_SZ;

    // Pre-split + tile operands (x: hi+lo; weights: hi only, fused launch)
    split_tiled<<<M_SZ, 256>>>(x, xh, xl, M_SZ);
    dim3 gw(D_SZ, 4);
    split_tiled_w<<<gw, 256>>>(Wq, Wk, Wv, Wo, wh);

    // Fused Q/K/V projection
    dim3 gq(D_SZ / 128, M_SZ / 128, 3);    // (16, 32, 3)
    gemm7<<<gq, 256, G7_SMEM>>>(xh, xl, wh, q_ptr, k_ptr, v_ptr, D_SZ);

    // RoPE + convert to tiled fp16 (Q hi scaled, K hi, V hi)
    rope_convert<<<(M_SZ * H_SZ * 8) / 256, 256>>>(q_ptr, k_ptr, v_ptr,
                                                   qhp, khp, vhp);

    dim3 ga(N_SZ / 128, B_SZ * H_SZ);      // (16, 32)
    attn3<<<ga, 256, ATT3_SMEM>>>(qhp, khp, vhp, oh);

    // O projection (single-MMA, A = O hi)
    dim3 go(D_SZ / 128, M_SZ / 128, 1);
    gemm8<<<go, 256, G8_SMEM>>>(oh, wh + 3 * woff, out, D_SZ);
}